// round 10
// baseline (speedup 1.0000x reference)
#include <cuda_runtime.h>
#include <cuda_bf16.h>
#include <cstdint>

// Problem constants (fixed by the reference)
constexpr int N_   = 50000;
constexpr int E_   = 800000;
constexpr int EP_  = E_ + N_;      // edges + self loops = 850000
constexpr int C_   = 128;          // feature dim (HEADS*HID)
constexpr int H_   = 4;            // heads
constexpr int HID_ = 32;
constexpr int B_   = 100;
constexpr int NF_  = 15;
constexpr float NEG_SLOPE = 0.2f;

// ---------------- scratch (static device globals; no allocation) ----------------
__device__ __align__(16) float g_xh[(size_t)N_ * C_];   // transformed features [N,128]
__device__ __align__(16) float g_h[(size_t)N_ * C_];    // layer-1 output (hidden)
__device__ __align__(16) float g_asrc[N_ * H_];
__device__ __align__(16) float g_adst[N_ * H_];
__device__ int   g_rowptr[N_ + 1];
__device__ int   g_cursor[N_];       // degree buffer, then write cursor
__device__ int   g_csr_src[EP_];
__device__ __align__(16) float g_pool[B_ * HID_];
__device__ float g_cnt[B_];

// ---------------- helpers ----------------
__device__ __forceinline__ float lrelu(float x) {
    return x > 0.f ? x : NEG_SLOPE * x;
}

// ---------------- CSR build ----------------

__global__ void k_zero_pool_deg() {
    int i = blockIdx.x * blockDim.x + threadIdx.x;
    if (i < B_ * HID_) g_pool[i] = 0.f;
    if (i < B_)        g_cnt[i]  = 0.f;
    if (i < N_)        g_cursor[i] = 1;   // degree starts at 1 (self loop)
}

__global__ void k_hist(const int* __restrict__ ei) {
    int e = blockIdx.x * blockDim.x + threadIdx.x;
    if (e < E_) atomicAdd(&g_cursor[ei[E_ + e]], 1);
}

// Single-block exclusive scan of degrees into g_rowptr. Also places the
// self-loop in slot 0 of each row and sets the scatter cursor past it.
__global__ void __launch_bounds__(1024) k_scan() {
    __shared__ int ssum[1024];
    int t = threadIdx.x;
    constexpr int PER = (N_ + 1023) / 1024;   // 49
    int lo = t * PER;
    int hi = min(lo + PER, N_);
    int s = 0;
    for (int i = lo; i < hi; i++) s += g_cursor[i];
    ssum[t] = s;
    __syncthreads();
    for (int off = 1; off < 1024; off <<= 1) {
        int u = (t >= off) ? ssum[t - off] : 0;
        __syncthreads();
        ssum[t] += u;
        __syncthreads();
    }
    int run = ssum[t] - s;     // exclusive base for this segment
    for (int i = lo; i < hi; i++) {
        int dg = g_cursor[i];          // read BEFORE overwriting
        g_rowptr[i]  = run;
        g_csr_src[run] = i;            // self loop in slot 0
        g_cursor[i]  = run + 1;        // scatter cursor past self loop
        run += dg;
    }
    if (t == 1023) g_rowptr[N_] = ssum[1023];
}

__global__ void k_scatter(const int* __restrict__ ei) {
    int e = blockIdx.x * blockDim.x + threadIdx.x;
    if (e >= E_) return;
    int s = ei[e], d = ei[E_ + e];
    int pos = atomicAdd(&g_cursor[d], 1);
    g_csr_src[pos] = s;
}

// ---------------- Register-tiled GEMM + fused attention dots ----------------
// C = X @ W  (X:[N,128], W:[128,128]) -> g_xh, plus
// a_src[n,h] = sum_c C[n, h*32+c]*attS[h*32+c], a_dst likewise.
// X==nullptr means "use g_h as input" (layer 2).
// Block: 256 threads, tile 128 rows x 128 cols, 8x8 microtile.
// NOTE: no min-blocks in launch_bounds -> ptxas may use up to 255 regs, no spill.
__global__ void __launch_bounds__(256) k_gemm_tiled(
    const float* __restrict__ X,
    const float* __restrict__ W,
    const float* __restrict__ attS,
    const float* __restrict__ attD)
{
    __shared__ float As[16][128];   // [k][row]  (transposed for broadcast LDS)
    __shared__ float Bs[16][128];   // [k][col]
    const float* Xp = X ? X : g_h;
    int tid = threadIdx.x;
    int tx = tid & 15;              // col group: cols tx*8..tx*8+7
    int ty = tid >> 4;              // row group: rows ty*8..ty*8+7
    int row0 = blockIdx.x * 128;

    float acc[8][8];
    #pragma unroll
    for (int i = 0; i < 8; i++)
        #pragma unroll
        for (int j = 0; j < 8; j++) acc[i][j] = 0.f;

    for (int kc = 0; kc < 128; kc += 16) {
        // A tile: 128 rows x 16 k, stored transposed As[k][row]
        #pragma unroll
        for (int u = 0; u < 2; u++) {
            int f  = tid + u * 256;            // 0..511 float4 slots
            int rr = f >> 2;                   // row in tile 0..127
            int k4 = f & 3;                    // which float4 along k
            int grow = min(row0 + rr, N_ - 1); // clamp (stores are guarded)
            float4 v = *(const float4*)&Xp[(size_t)grow * C_ + kc + k4 * 4];
            As[k4 * 4 + 0][rr] = v.x;
            As[k4 * 4 + 1][rr] = v.y;
            As[k4 * 4 + 2][rr] = v.z;
            As[k4 * 4 + 3][rr] = v.w;
        }
        // B tile: 16 k x 128 cols, direct copy
        #pragma unroll
        for (int u = 0; u < 2; u++) {
            int f  = tid + u * 256;
            int kk = f >> 5;                   // 0..15
            int c4 = f & 31;
            *(float4*)&Bs[kk][c4 * 4] =
                *(const float4*)&W[(size_t)(kc + kk) * C_ + c4 * 4];
        }
        __syncthreads();
        #pragma unroll
        for (int k = 0; k < 16; k++) {
            float a[8], b[8];
            *(float4*)&a[0] = *(const float4*)&As[k][ty * 8];
            *(float4*)&a[4] = *(const float4*)&As[k][ty * 8 + 4];
            *(float4*)&b[0] = *(const float4*)&Bs[k][tx * 8];
            *(float4*)&b[4] = *(const float4*)&Bs[k][tx * 8 + 4];
            #pragma unroll
            for (int i = 0; i < 8; i++)
                #pragma unroll
                for (int j = 0; j < 8; j++)
                    acc[i][j] += a[i] * b[j];
        }
        __syncthreads();
    }

    // Epilogue: store C rows + fused attention dot partials.
    float s_att[8], d_att[8];
    #pragma unroll
    for (int i = 0; i < 8; i++) {
        float ps = 0.f, pd = 0.f;
        #pragma unroll
        for (int j = 0; j < 8; j++) {
            float av = acc[i][j];
            ps += av * attS[tx * 8 + j];
            pd += av * attD[tx * 8 + j];
        }
        s_att[i] = ps;
        d_att[i] = pd;
        int row = row0 + ty * 8 + i;
        if (row < N_) {
            *(float4*)&g_xh[(size_t)row * C_ + tx * 8]     = *(float4*)&acc[i][0];
            *(float4*)&g_xh[(size_t)row * C_ + tx * 8 + 4] = *(float4*)&acc[i][4];
        }
    }
    // Reduce across the 4 threads of each head group (tx in {4h..4h+3} are
    // consecutive lanes), then lane tx%4==0 writes the per-head dot.
    #pragma unroll
    for (int m = 1; m <= 2; m <<= 1) {
        #pragma unroll
        for (int i = 0; i < 8; i++) {
            s_att[i] += __shfl_xor_sync(0xffffffffu, s_att[i], m);
            d_att[i] += __shfl_xor_sync(0xffffffffu, d_att[i], m);
        }
    }
    if ((tx & 3) == 0) {
        int head = tx >> 2;
        #pragma unroll
        for (int i = 0; i < 8; i++) {
            int row = row0 + ty * 8 + i;
            if (row < N_) {
                g_asrc[row * H_ + head] = s_att[i];
                g_adst[row * H_ + head] = d_att[i];
            }
        }
    }
}

// ---------------- CSR aggregation: one warp per dst node, no atomics on features.
// Softmax shift-invariance: logits tiny (|e|<~10) -> no max pass; normalize at end.
// LAYER 1: write relu(agg/denom + b1) to g_h.
// LAYER 2: head-mean via shfl, atomic into graph pool (no feature write at all).
template<int LAYER>
__global__ void __launch_bounds__(256) k_csr_agg(
    const float* __restrict__ bias,
    const int*   __restrict__ batch)
{
    int warp = (blockIdx.x * blockDim.x + threadIdx.x) >> 5;
    if (warp >= N_) return;
    int lane = threadIdx.x & 31;
    int head = lane >> 3;
    int n = warp;

    float adv = g_adst[n * H_ + head];
    int beg = g_rowptr[n];
    int end = g_rowptr[n + 1];

    float a0 = 0.f, a1 = 0.f, a2 = 0.f, a3 = 0.f, dsum = 0.f;

    int j = beg;
    // 4-deep unroll: four independent gather chains in flight
    for (; j + 3 < end; j += 4) {
        int s0 = g_csr_src[j];
        int s1 = g_csr_src[j + 1];
        int s2 = g_csr_src[j + 2];
        int s3 = g_csr_src[j + 3];
        float e0 = __expf(lrelu(g_asrc[s0 * H_ + head] + adv));
        float e1 = __expf(lrelu(g_asrc[s1 * H_ + head] + adv));
        float e2 = __expf(lrelu(g_asrc[s2 * H_ + head] + adv));
        float e3 = __expf(lrelu(g_asrc[s3 * H_ + head] + adv));
        float4 x0 = *(const float4*)&g_xh[(size_t)s0 * C_ + lane * 4];
        float4 x1 = *(const float4*)&g_xh[(size_t)s1 * C_ + lane * 4];
        float4 x2 = *(const float4*)&g_xh[(size_t)s2 * C_ + lane * 4];
        float4 x3 = *(const float4*)&g_xh[(size_t)s3 * C_ + lane * 4];
        a0 += e0 * x0.x + e1 * x1.x + e2 * x2.x + e3 * x3.x;
        a1 += e0 * x0.y + e1 * x1.y + e2 * x2.y + e3 * x3.y;
        a2 += e0 * x0.z + e1 * x1.z + e2 * x2.z + e3 * x3.z;
        a3 += e0 * x0.w + e1 * x1.w + e2 * x2.w + e3 * x3.w;
        dsum += (e0 + e1) + (e2 + e3);
    }
    for (; j < end; j++) {
        int s0 = g_csr_src[j];
        float e0 = __expf(lrelu(g_asrc[s0 * H_ + head] + adv));
        float4 x0 = *(const float4*)&g_xh[(size_t)s0 * C_ + lane * 4];
        a0 += e0 * x0.x; a1 += e0 * x0.y; a2 += e0 * x0.z; a3 += e0 * x0.w;
        dsum += e0;
    }

    float inv = 1.f / (dsum + 1e-16f);
    if (LAYER == 1) {
        float4 o;
        o.x = fmaxf(a0 * inv + bias[lane * 4 + 0], 0.f);
        o.y = fmaxf(a1 * inv + bias[lane * 4 + 1], 0.f);
        o.z = fmaxf(a2 * inv + bias[lane * 4 + 2], 0.f);
        o.w = fmaxf(a3 * inv + bias[lane * 4 + 3], 0.f);
        *(float4*)&g_h[(size_t)n * C_ + lane * 4] = o;
    } else {
        float v0 = a0 * inv, v1 = a1 * inv, v2 = a2 * inv, v3 = a3 * inv;
        // sum across the 4 heads: lanes l, l^8, l^16, l^24 hold the same hidden channel
        #pragma unroll
        for (int m = 8; m <= 16; m <<= 1) {
            v0 += __shfl_xor_sync(0xffffffffu, v0, m);
            v1 += __shfl_xor_sync(0xffffffffu, v1, m);
            v2 += __shfl_xor_sync(0xffffffffu, v2, m);
            v3 += __shfl_xor_sync(0xffffffffu, v3, m);
        }
        if (lane < 8) {
            int b = batch[n];
            float4 p;
            p.x = 0.25f * v0 + bias[lane * 4 + 0];
            p.y = 0.25f * v1 + bias[lane * 4 + 1];
            p.z = 0.25f * v2 + bias[lane * 4 + 2];
            p.w = 0.25f * v3 + bias[lane * 4 + 3];
            atomicAdd((float4*)&g_pool[b * HID_ + lane * 4], p);
            if (lane == 0) atomicAdd(&g_cnt[b], 1.f);
        }
    }
}

// Final MLP: one warp per graph. [32 pooled | 15 stats] -> 32 -> 1
__global__ void k_mlp(const float* __restrict__ stats,
                      const float* __restrict__ Wm1, const float* __restrict__ bm1,
                      const float* __restrict__ Wm2, const float* __restrict__ bm2,
                      float* __restrict__ out)
{
    int b = blockIdx.x;
    int t = threadIdx.x;
    __shared__ float gv[HID_ + NF_ + 1];
    float cnt = fmaxf(g_cnt[b], 1.f);
    gv[t] = g_pool[b * HID_ + t] / cnt;
    if (t < NF_) gv[HID_ + t] = stats[b * NF_ + t];
    __syncwarp();
    float h = bm1[t];
    #pragma unroll
    for (int i = 0; i < HID_ + NF_; i++) h += gv[i] * Wm1[i * HID_ + t];
    h = fmaxf(h, 0.f);
    float o = h * Wm2[t];
    #pragma unroll
    for (int off = 16; off > 0; off >>= 1) o += __shfl_down_sync(0xffffffffu, o, off);
    if (t == 0) out[b] = o + bm2[0];
}

// ---------------- launch ----------------
extern "C" void kernel_launch(void* const* d_in, const int* in_sizes, int n_in,
                              void* d_out, int out_size)
{
    const float* x     = (const float*)d_in[0];
    const int*   ei    = (const int*)d_in[1];      // int32 (JAX x64 disabled)
    const int*   batch = (const int*)d_in[2];      // int32
    const float* stats = (const float*)d_in[3];
    const float* W1    = (const float*)d_in[4];
    const float* as1   = (const float*)d_in[5];
    const float* ad1   = (const float*)d_in[6];
    const float* b1    = (const float*)d_in[7];
    const float* W2    = (const float*)d_in[8];
    const float* as2   = (const float*)d_in[9];
    const float* ad2   = (const float*)d_in[10];
    const float* b2    = (const float*)d_in[11];
    const float* Wm1   = (const float*)d_in[12];
    const float* bm1   = (const float*)d_in[13];
    const float* Wm2   = (const float*)d_in[14];
    const float* bm2   = (const float*)d_in[15];
    float*       out   = (float*)d_out;

    const int T = 256;
    auto cdiv = [](long long a, long long b) { return (int)((a + b - 1) / b); };
    const int GEMM_BLOCKS = cdiv(N_, 128);   // 391

    // ---- CSR build (also zeroes pool/cnt; scan places self loops) ----
    k_zero_pool_deg<<<cdiv(N_, T), T>>>();
    k_hist<<<cdiv(E_, T), T>>>(ei);
    k_scan<<<1, 1024>>>();
    k_scatter<<<cdiv(E_, T), T>>>(ei);

    // ---- layer 1 ----
    k_gemm_tiled<<<GEMM_BLOCKS, 256>>>(x, W1, as1, ad1);
    k_csr_agg<1><<<cdiv((long long)N_ * 32, T), T>>>(b1, nullptr);

    // ---- layer 2 (input selected in-kernel: X==nullptr -> g_h) ----
    k_gemm_tiled<<<GEMM_BLOCKS, 256>>>(nullptr, W2, as2, ad2);
    k_csr_agg<2><<<cdiv((long long)N_ * 32, T), T>>>(b2, batch);

    // ---- MLP ----
    k_mlp<<<B_, HID_>>>(stats, Wm1, bm1, Wm2, bm2, out);
}